// round 8
// baseline (speedup 1.0000x reference)
#include <cuda_runtime.h>
#include <cuda_fp16.h>
#include <cstdint>
#include <cstddef>

#define T_TOK 8192
#define DIN   4096
#define DOUT  4096
#define NE    8
#define ER    128          // E * R
#define KCAT  4224         // DIN + ER
#define SCALING 2.0f

// ---------------------------------------------------------------------------
// Scratch (device globals; no allocations allowed)
// ---------------------------------------------------------------------------
__device__ __align__(128) __half g_xf[(size_t)T_TOK * KCAT];
__device__ __align__(128) __half g_wf[(size_t)DOUT * KCAT];
__device__ __align__(128) __half g_af[(size_t)ER * DIN];
__device__ float g_logits[(size_t)T_TOK * NE];

// ---------------------------------------------------------------------------
// PTX primitives (baseline sm_80+)
// ---------------------------------------------------------------------------
__device__ __forceinline__ uint32_t smem_u32(const void* p) {
    uint32_t a;
    asm("{ .reg .u64 t; cvta.to.shared.u64 t, %1; cvt.u32.u64 %0, t; }"
        : "=r"(a) : "l"(p));
    return a;
}
__device__ __forceinline__ void cp16(uint32_t s, const void* g) {
    asm volatile("cp.async.cg.shared.global [%0], [%1], 16;" :: "r"(s), "l"(g));
}
#define CP_COMMIT() asm volatile("cp.async.commit_group;" ::: "memory")
#define CP_WAIT(n)  asm volatile("cp.async.wait_group %0;" :: "n"(n) : "memory")

__device__ __forceinline__ void ldsm4(uint32_t* r, uint32_t addr) {
    asm volatile("ldmatrix.sync.aligned.m8n8.x4.shared.b16 {%0,%1,%2,%3}, [%4];"
                 : "=r"(r[0]), "=r"(r[1]), "=r"(r[2]), "=r"(r[3]) : "r"(addr));
}
__device__ __forceinline__ void mma16816(float* d, const uint32_t* a,
                                         const uint32_t* b) {
    asm volatile(
        "mma.sync.aligned.m16n8k16.row.col.f32.f16.f16.f32 "
        "{%0,%1,%2,%3}, {%4,%5,%6,%7}, {%8,%9}, {%0,%1,%2,%3};"
        : "+f"(d[0]), "+f"(d[1]), "+f"(d[2]), "+f"(d[3])
        : "r"(a[0]), "r"(a[1]), "r"(a[2]), "r"(a[3]), "r"(b[0]), "r"(b[1]));
}

// ---------------------------------------------------------------------------
// fp16 GEMM: C[M,N] = A @ B^T. Block tile 128 x BN, THREADS/32 warps in a
// 2 x (WARPS/2) grid, warp tile 64 x WN. BK = 128 halves, 2-stage cp.async.
// Latency hiding comes from warp count (4 warps/SMSP at THREADS=512), so
// fragments are single-buffered (keeps regs <= 128/thread, no spills).
// Synchronization (canonical, two barriers per chunk):
//   CP_WAIT(1); __syncthreads();   -> chunk c visible to ALL warps
//   consume stage s;  __syncthreads();  stage_load(c+2 -> s)
// Smem pitch 272 B: conflict-free for cp.async stores and ldmatrix reads.
// EPI 0: +bias, fp32 C.   EPI 1: MoE routing epilogue -> fp16 G cols of g_xf.
// ---------------------------------------------------------------------------
#define PITCH 272

template <int K_TOT, int BN, int EPI, int THREADS>
__global__ void __launch_bounds__(THREADS, 1)
gemm_mma(const __half* __restrict__ A, const __half* __restrict__ B,
         const float* __restrict__ bias, float* __restrict__ C,
         int ldc, int lda, int ldb) {
    constexpr int NCH     = K_TOT / 128;
    constexpr int ROWS    = 128 + BN;
    constexpr int STAGE_B = ROWS * PITCH;
    constexpr int NWARPS  = THREADS / 32;
    constexpr int WN      = BN / (NWARPS / 2);   // 32
    constexpr int NP      = WN / 16;             // B ldsm4 per k16 (2)
    constexpr int LPT     = ROWS * 16 / THREADS; // cp16 per thread per stage

    extern __shared__ char sm[];
    const uint32_t base = smem_u32(sm);

    const int tid  = threadIdx.x;
    const int wid  = tid >> 5;
    const int lane = tid & 31;
    const int bm = blockIdx.x * 128;
    const int bn = blockIdx.y * BN;
    const int wm = (wid & 1) * 64;
    const int wn = (wid >> 1) * WN;

    auto stage_load = [&](int c, int s) {
        const int kk = c * 128;
        const uint32_t sb = base + s * STAGE_B;
#pragma unroll
        for (int i = 0; i < LPT; ++i) {
            int idx  = tid + i * THREADS;
            int row  = idx >> 4;
            int part = idx & 15;
            const __half* g = (row < 128)
                ? A + (size_t)(bm + row) * lda + kk + part * 8
                : B + (size_t)(bn + row - 128) * ldb + kk + part * 8;
            cp16(sb + row * PITCH + part * 16, g);
        }
        CP_COMMIT();
    };

    float acc[4][2 * NP][4];
#pragma unroll
    for (int i = 0; i < 4; i++)
#pragma unroll
        for (int j = 0; j < 2 * NP; j++)
#pragma unroll
            for (int k = 0; k < 4; k++) acc[i][j][k] = 0.f;

    stage_load(0, 0);
    stage_load(1, 1);

    const uint32_t a_off = (wm + (lane & 15)) * PITCH + (lane >> 4) * 16;
    const uint32_t b_row = wn + (lane & 7) + ((lane >> 4) & 1) * 8;
    const uint32_t b_off = b_row * PITCH + ((lane >> 3) & 1) * 16;

    for (int c = 0; c < NCH; ++c) {
        const int s = c & 1;
        // CP_WAIT certifies this thread's chunk-c group; the barrier makes
        // every thread's chunk-c data visible to every warp.
        CP_WAIT(1);
        __syncthreads();

        const uint32_t sA = base + s * STAGE_B;
        const uint32_t sB = sA + 128 * PITCH;

#pragma unroll
        for (int ks = 0; ks < 8; ++ks) {
            uint32_t aF[4][4];
            uint32_t bF[NP][4];
#pragma unroll
            for (int mf = 0; mf < 4; ++mf)
                ldsm4(aF[mf], sA + a_off + mf * (16 * PITCH) + ks * 32);
#pragma unroll
            for (int p = 0; p < NP; ++p)
                ldsm4(bF[p], sB + b_off + p * (16 * PITCH) + ks * 32);
#pragma unroll
            for (int mf = 0; mf < 4; ++mf)
#pragma unroll
                for (int p = 0; p < NP; ++p) {
                    mma16816(acc[mf][2 * p + 0], aF[mf], &bF[p][0]);
                    mma16816(acc[mf][2 * p + 1], aF[mf], &bF[p][2]);
                }
        }

        // all warps done reading stage s -> safe to overwrite with chunk c+2
        __syncthreads();
        if (c + 2 < NCH) stage_load(c + 2, s);
        else CP_COMMIT();   // keep one commit per iteration (wait invariant)
    }

    const int row0 = wm + (lane >> 2);
    const int col0 = wn + (lane & 3) * 2;

    if (EPI == 0) {
        // bias + fp32 store
#pragma unroll
        for (int mf = 0; mf < 4; ++mf) {
#pragma unroll
            for (int r8 = 0; r8 < 2; ++r8) {
                int row = bm + row0 + mf * 16 + r8 * 8;
                float* Cr = C + (size_t)row * ldc;
#pragma unroll
                for (int nf = 0; nf < 2 * NP; ++nf) {
                    int col = bn + col0 + nf * 8;
                    float2 v;
                    v.x = acc[mf][nf][r8 * 2 + 0];
                    v.y = acc[mf][nf][r8 * 2 + 1];
                    v.x += bias[col]; v.y += bias[col + 1];
                    *(float2*)(Cr + col) = v;
                }
            }
        }
    } else {
        // Routing epilogue: h -> weighted fp16 G columns of g_xf.
        __shared__ float s_w1[128], s_w2[128];
        __shared__ int   s_i1[128], s_i2[128];
        __syncthreads();
        if (tid < 128) {
            const int t = bm + tid;
            float l[NE];
#pragma unroll
            for (int e = 0; e < NE; ++e) l[e] = g_logits[(size_t)t * NE + e];
            float best = -1e30f; int i1 = 0;
#pragma unroll
            for (int e = 0; e < NE; ++e)
                if (l[e] > best) { best = l[e]; i1 = e; }
            float second = -1e30f; int i2 = 0;
#pragma unroll
            for (int e = 0; e < NE; ++e) {
                if (e == i1) continue;
                if (l[e] > second) { second = l[e]; i2 = e; }
            }
            float r  = expf(second - best);
            float w1 = 1.0f / (1.0f + r);
            s_w1[tid] = SCALING * w1;
            s_w2[tid] = SCALING * r * w1;
            s_i1[tid] = i1;
            s_i2[tid] = i2;
        }
        __syncthreads();
#pragma unroll
        for (int mf = 0; mf < 4; ++mf) {
#pragma unroll
            for (int r8 = 0; r8 < 2; ++r8) {
                int rl = row0 + mf * 16 + r8 * 8;
                int t  = bm + rl;
                float sw1 = s_w1[rl], sw2 = s_w2[rl];
                int i1 = s_i1[rl], i2 = s_i2[rl];
                __half* dst = g_xf + (size_t)t * KCAT + DIN;
#pragma unroll
                for (int nf = 0; nf < 2 * NP; ++nf) {
                    int col = col0 + nf * 8;  // 0..127, even
                    int e = col >> 4;
                    float m = (e == i1) ? sw1 : ((e == i2) ? sw2 : 0.f);
                    __half2 hv;
                    hv.x = __float2half_rn(m * acc[mf][nf][r8 * 2 + 0]);
                    hv.y = __float2half_rn(m * acc[mf][nf][r8 * 2 + 1]);
                    *(__half2*)(dst + col) = hv;
                }
            }
        }
    }
}

// ---------------------------------------------------------------------------
// Fused: x fp32->fp16 (into g_xf cols [0:4096)) + router logits.
// ---------------------------------------------------------------------------
__global__ void __launch_bounds__(256)
convx_router_kernel(const float* __restrict__ x, const float* __restrict__ Wr) {
    const int wid  = threadIdx.x >> 5;
    const int lane = threadIdx.x & 31;
    const int t = blockIdx.x * 8 + wid;
    const float* xr = x + (size_t)t * DIN;
    __half* xo = g_xf + (size_t)t * KCAT;

    float acc[NE];
#pragma unroll
    for (int e = 0; e < NE; ++e) acc[e] = 0.f;

#pragma unroll 4
    for (int i = 0; i < 32; ++i) {
        int off = i * 128 + lane * 4;
        float4 v = *(const float4*)(xr + off);
        __half2 h0, h1;
        h0.x = __float2half_rn(v.x); h0.y = __float2half_rn(v.y);
        h1.x = __float2half_rn(v.z); h1.y = __float2half_rn(v.w);
        uint2 pk;
        pk.x = *(const uint32_t*)&h0;
        pk.y = *(const uint32_t*)&h1;
        *(uint2*)(xo + off) = pk;
#pragma unroll
        for (int e = 0; e < NE; ++e) {
            float4 w = *(const float4*)(Wr + (size_t)e * DIN + off);
            acc[e] += v.x * w.x + v.y * w.y + v.z * w.z + v.w * w.w;
        }
    }
#pragma unroll
    for (int e = 0; e < NE; ++e) {
#pragma unroll
        for (int off = 16; off > 0; off >>= 1)
            acc[e] += __shfl_xor_sync(0xffffffffu, acc[e], off);
    }
    if (lane == 0) {
#pragma unroll
        for (int e = 0; e < NE; ++e) g_logits[(size_t)t * NE + e] = acc[e];
    }
}

// ---------------------------------------------------------------------------
// Fused weight prep: Wb -> g_wf[:, 0:4096), A -> g_af, Bm -> g_wf[:, 4096:).
// ---------------------------------------------------------------------------
__global__ void __launch_bounds__(256)
convw_kernel(const float* __restrict__ Wb, const float* __restrict__ A,
             const float* __restrict__ Bm) {
    const long long N1 = (long long)DOUT * (DIN / 4);
    const long long N2 = (long long)ER * (DIN / 4);
    const long long N3 = (long long)DOUT * ER;
    long long i = (long long)blockIdx.x * 256 + threadIdx.x;
    if (i < N1) {
        long long r = i / (DIN / 4);
        int c4 = (int)(i % (DIN / 4));
        float4 v = *(const float4*)(Wb + r * DIN + 4 * c4);
        __half2 h0, h1;
        h0.x = __float2half_rn(v.x); h0.y = __float2half_rn(v.y);
        h1.x = __float2half_rn(v.z); h1.y = __float2half_rn(v.w);
        uint2 pk;
        pk.x = *(const uint32_t*)&h0;
        pk.y = *(const uint32_t*)&h1;
        *(uint2*)(g_wf + r * KCAT + 4 * c4) = pk;
    } else if (i < N1 + N2) {
        long long j = i - N1;
        float4 v = *(const float4*)(A + 4 * j);
        __half2 h0, h1;
        h0.x = __float2half_rn(v.x); h0.y = __float2half_rn(v.y);
        h1.x = __float2half_rn(v.z); h1.y = __float2half_rn(v.w);
        uint2 pk;
        pk.x = *(const uint32_t*)&h0;
        pk.y = *(const uint32_t*)&h1;
        *(uint2*)(g_af + 4 * j) = pk;
    } else if (i < N1 + N2 + N3) {
        long long j = i - N1 - N2;
        int o = (int)(j >> 7);
        int c = (int)(j & 127);
        int e = c >> 4;
        int r = c & 15;
        g_wf[(size_t)o * KCAT + DIN + c] =
            __float2half_rn(Bm[((size_t)e * DOUT + o) * 16 + r]);
    }
}

// ---------------------------------------------------------------------------
// Host launcher — exactly 4 launches; main GEMM is the 4th (profiled).
// ---------------------------------------------------------------------------
constexpr int SMEM_MAIN = 2 * (128 + 256) * PITCH;  // 208896
constexpr int SMEM_H    = 2 * (128 + 128) * PITCH;  // 139264

extern "C" void kernel_launch(void* const* d_in, const int* in_sizes, int n_in,
                              void* d_out, int out_size) {
    const float* x    = (const float*)d_in[0];
    const float* Wb   = (const float*)d_in[1];
    const float* bias = (const float*)d_in[2];
    const float* Wr   = (const float*)d_in[3];
    const float* A    = (const float*)d_in[4];
    const float* Bm   = (const float*)d_in[5];
    float* out = (float*)d_out;

    void *p_xf, *p_wf, *p_af;
    cudaGetSymbolAddress(&p_xf, g_xf);
    cudaGetSymbolAddress(&p_wf, g_wf);
    cudaGetSymbolAddress(&p_af, g_af);

    static bool attr_set = false;
    if (!attr_set) {
        cudaFuncSetAttribute(gemm_mma<KCAT, 256, 0, 512>,
                             cudaFuncAttributeMaxDynamicSharedMemorySize, SMEM_MAIN);
        cudaFuncSetAttribute(gemm_mma<DIN, 128, 1, 256>,
                             cudaFuncAttributeMaxDynamicSharedMemorySize, SMEM_H);
        attr_set = true;
    }

    // 1) x -> fp16 + router logits
    convx_router_kernel<<<T_TOK / 8, 256>>>(x, Wr);

    // 2) Wb / A / Bflat -> fp16
    {
        long long total = (long long)DOUT * (DIN / 4) + (long long)ER * (DIN / 4)
                        + (long long)DOUT * ER;
        convw_kernel<<<(unsigned)((total + 255) / 256), 256>>>(Wb, A, Bm);
    }

    // 3) h = x @ A^T  fused with routing -> G columns of g_xf
    //    (256 threads: 8 warps, warp tile 64x32 over BN=128)
    {
        dim3 grid(T_TOK / 128, 1);
        gemm_mma<DIN, 128, 1, 256><<<grid, 256, SMEM_H>>>(
            (const __half*)p_xf, (const __half*)p_af,
            nullptr, nullptr, 0, KCAT, DIN);
    }

    // 4) out = [x|G] @ [Wb|Bf]^T + bias   (512 threads, 16 warps; profiled)
    {
        dim3 grid(T_TOK / 128, DOUT / 256);
        gemm_mma<KCAT, 256, 0, 512><<<grid, 512, SMEM_MAIN>>>(
            (const __half*)p_xf, (const __half*)p_wf,
            bias, out, DOUT, KCAT, KCAT);
    }
}

// round 9
// speedup vs baseline: 1.5407x; 1.5407x over previous
#include <cuda_runtime.h>
#include <cuda_fp16.h>
#include <cstdint>
#include <cstddef>

#define T_TOK 8192
#define DIN   4096
#define DOUT  4096
#define NE    8
#define ER    128          // E * R
#define KCAT  4224         // DIN + ER
#define SCALING 2.0f

// ---------------------------------------------------------------------------
// Scratch (device globals; no allocations allowed)
// ---------------------------------------------------------------------------
__device__ __align__(128) __half g_xf[(size_t)T_TOK * KCAT];
__device__ __align__(128) __half g_wf[(size_t)DOUT * KCAT];
__device__ __align__(128) __half g_af[(size_t)ER * DIN];
__device__ float g_logits[(size_t)T_TOK * NE];

// ---------------------------------------------------------------------------
// PTX primitives (baseline sm_80+)
// ---------------------------------------------------------------------------
__device__ __forceinline__ uint32_t smem_u32(const void* p) {
    uint32_t a;
    asm("{ .reg .u64 t; cvta.to.shared.u64 t, %1; cvt.u32.u64 %0, t; }"
        : "=r"(a) : "l"(p));
    return a;
}
__device__ __forceinline__ void cp16(uint32_t s, const void* g) {
    asm volatile("cp.async.cg.shared.global [%0], [%1], 16;" :: "r"(s), "l"(g));
}
#define CP_COMMIT() asm volatile("cp.async.commit_group;" ::: "memory")
#define CP_WAIT(n)  asm volatile("cp.async.wait_group %0;" :: "n"(n) : "memory")

__device__ __forceinline__ void ldsm4(uint32_t* r, uint32_t addr) {
    asm volatile("ldmatrix.sync.aligned.m8n8.x4.shared.b16 {%0,%1,%2,%3}, [%4];"
                 : "=r"(r[0]), "=r"(r[1]), "=r"(r[2]), "=r"(r[3]) : "r"(addr));
}
__device__ __forceinline__ void mma16816(float* d, const uint32_t* a,
                                         const uint32_t* b) {
    asm volatile(
        "mma.sync.aligned.m16n8k16.row.col.f32.f16.f16.f32 "
        "{%0,%1,%2,%3}, {%4,%5,%6,%7}, {%8,%9}, {%0,%1,%2,%3};"
        : "+f"(d[0]), "+f"(d[1]), "+f"(d[2]), "+f"(d[3])
        : "r"(a[0]), "r"(a[1]), "r"(a[2]), "r"(a[3]), "r"(b[0]), "r"(b[1]));
}

// ---------------------------------------------------------------------------
// fp16 GEMM (R7-proven): C[M,N] = A @ B^T. Block tile 128 x BN, 8 warps
// (2 x 4), warp tile 64 x (BN/4). BK = 128 halves, 2-stage cp.async,
// register double-buffered fragments, two barriers per chunk (canonical
// cp.async visibility pattern). Smem pitch 272 B: conflict-free for cp.async
// stores and ldmatrix reads.
// Block index mapping: blockIdx.x = n-tile (fast), blockIdx.y = m-tile, so
// consecutive CTAs in a wave share the same A tile (L2/DRAM reuse).
// EPI 0: +bias, fp32 C.   EPI 1: MoE routing epilogue -> fp16 G cols of g_xf.
// ---------------------------------------------------------------------------
#define PITCH 272

template <int K_TOT, int BN, int EPI>
__global__ void __launch_bounds__(256, 1)
gemm_mma(const __half* __restrict__ A, const __half* __restrict__ B,
         const float* __restrict__ bias, float* __restrict__ C,
         int ldc, int lda, int ldb) {
    constexpr int NCH     = K_TOT / 128;
    constexpr int ROWS    = 128 + BN;
    constexpr int STAGE_B = ROWS * PITCH;
    constexpr int WN      = BN / 4;
    constexpr int NP      = WN / 16;         // B ldsm4 per k16 (4 or 2)
    constexpr int LPT     = ROWS / 16;       // cp16 per thread per stage

    extern __shared__ char sm[];
    const uint32_t base = smem_u32(sm);

    const int tid  = threadIdx.x;
    const int wid  = tid >> 5;
    const int lane = tid & 31;
    const int bm = blockIdx.y * 128;   // m-tile on slow axis
    const int bn = blockIdx.x * BN;    // n-tile on fast axis (A-tile reuse)
    const int wm = (wid & 1) * 64;
    const int wn = (wid >> 1) * WN;

    auto stage_load = [&](int c, int s) {
        const int kk = c * 128;
        const uint32_t sb = base + s * STAGE_B;
#pragma unroll
        for (int i = 0; i < LPT; ++i) {
            int idx  = tid + i * 256;
            int row  = idx >> 4;
            int part = idx & 15;
            const __half* g = (row < 128)
                ? A + (size_t)(bm + row) * lda + kk + part * 8
                : B + (size_t)(bn + row - 128) * ldb + kk + part * 8;
            cp16(sb + row * PITCH + part * 16, g);
        }
        CP_COMMIT();
    };

    float acc[4][2 * NP][4];
#pragma unroll
    for (int i = 0; i < 4; i++)
#pragma unroll
        for (int j = 0; j < 2 * NP; j++)
#pragma unroll
            for (int k = 0; k < 4; k++) acc[i][j][k] = 0.f;

    stage_load(0, 0);
    stage_load(1, 1);

    const uint32_t a_off = (wm + (lane & 15)) * PITCH + (lane >> 4) * 16;
    const uint32_t b_row = wn + (lane & 7) + ((lane >> 4) & 1) * 8;
    const uint32_t b_off = b_row * PITCH + ((lane >> 3) & 1) * 16;

    uint32_t aF[2][4][4];
    uint32_t bF[2][NP][4];

    for (int c = 0; c < NCH; ++c) {
        const int s = c & 1;
        // CP_WAIT certifies this thread's chunk-c group; the barrier makes
        // every thread's chunk-c data visible to every warp.
        CP_WAIT(1);
        __syncthreads();

        const uint32_t sA = base + s * STAGE_B;
        const uint32_t sB = sA + 128 * PITCH;

        // prime ks=0 frags
#pragma unroll
        for (int mf = 0; mf < 4; ++mf)
            ldsm4(aF[0][mf], sA + a_off + mf * (16 * PITCH));
#pragma unroll
        for (int p = 0; p < NP; ++p)
            ldsm4(bF[0][p], sB + b_off + p * (16 * PITCH));

#pragma unroll
        for (int ks = 0; ks < 8; ++ks) {
            const int cur = ks & 1, nxt = cur ^ 1;
            if (ks < 7) {
#pragma unroll
                for (int mf = 0; mf < 4; ++mf)
                    ldsm4(aF[nxt][mf], sA + a_off + mf * (16 * PITCH) + (ks + 1) * 32);
#pragma unroll
                for (int p = 0; p < NP; ++p)
                    ldsm4(bF[nxt][p], sB + b_off + p * (16 * PITCH) + (ks + 1) * 32);
            }
#pragma unroll
            for (int mf = 0; mf < 4; ++mf)
#pragma unroll
                for (int p = 0; p < NP; ++p) {
                    mma16816(acc[mf][2 * p + 0], aF[cur][mf], &bF[cur][p][0]);
                    mma16816(acc[mf][2 * p + 1], aF[cur][mf], &bF[cur][p][2]);
                }
        }

        // all warps done reading stage s -> safe to overwrite with chunk c+2
        __syncthreads();
        if (c + 2 < NCH) stage_load(c + 2, s);
        else CP_COMMIT();   // keep one commit per iteration (wait invariant)
    }

    const int row0 = wm + (lane >> 2);
    const int col0 = wn + (lane & 3) * 2;

    if (EPI == 0) {
        // bias + fp32 store
#pragma unroll
        for (int mf = 0; mf < 4; ++mf) {
#pragma unroll
            for (int r8 = 0; r8 < 2; ++r8) {
                int row = bm + row0 + mf * 16 + r8 * 8;
                float* Cr = C + (size_t)row * ldc;
#pragma unroll
                for (int nf = 0; nf < 2 * NP; ++nf) {
                    int col = bn + col0 + nf * 8;
                    float2 v;
                    v.x = acc[mf][nf][r8 * 2 + 0];
                    v.y = acc[mf][nf][r8 * 2 + 1];
                    v.x += bias[col]; v.y += bias[col + 1];
                    *(float2*)(Cr + col) = v;
                }
            }
        }
    } else {
        // Routing epilogue: h -> weighted fp16 G columns of g_xf.
        __shared__ float s_w1[128], s_w2[128];
        __shared__ int   s_i1[128], s_i2[128];
        __syncthreads();
        if (tid < 128) {
            const int t = bm + tid;
            float l[NE];
#pragma unroll
            for (int e = 0; e < NE; ++e) l[e] = g_logits[(size_t)t * NE + e];
            float best = -1e30f; int i1 = 0;
#pragma unroll
            for (int e = 0; e < NE; ++e)
                if (l[e] > best) { best = l[e]; i1 = e; }
            float second = -1e30f; int i2 = 0;
#pragma unroll
            for (int e = 0; e < NE; ++e) {
                if (e == i1) continue;
                if (l[e] > second) { second = l[e]; i2 = e; }
            }
            float r  = expf(second - best);
            float w1 = 1.0f / (1.0f + r);
            s_w1[tid] = SCALING * w1;
            s_w2[tid] = SCALING * r * w1;
            s_i1[tid] = i1;
            s_i2[tid] = i2;
        }
        __syncthreads();
#pragma unroll
        for (int mf = 0; mf < 4; ++mf) {
#pragma unroll
            for (int r8 = 0; r8 < 2; ++r8) {
                int rl = row0 + mf * 16 + r8 * 8;
                int t  = bm + rl;
                float sw1 = s_w1[rl], sw2 = s_w2[rl];
                int i1 = s_i1[rl], i2 = s_i2[rl];
                __half* dst = g_xf + (size_t)t * KCAT + DIN;
#pragma unroll
                for (int nf = 0; nf < 2 * NP; ++nf) {
                    int col = col0 + nf * 8;  // 0..127, even
                    int e = col >> 4;
                    float m = (e == i1) ? sw1 : ((e == i2) ? sw2 : 0.f);
                    __half2 hv;
                    hv.x = __float2half_rn(m * acc[mf][nf][r8 * 2 + 0]);
                    hv.y = __float2half_rn(m * acc[mf][nf][r8 * 2 + 1]);
                    *(__half2*)(dst + col) = hv;
                }
            }
        }
    }
}

// ---------------------------------------------------------------------------
// Merged prep kernel (single launch):
//   blocks [0, XB)          : x fp32->fp16 into g_xf[:, 0:4096) + router logits
//   blocks [XB, XB+WB)      : Wb -> g_wf[:, 0:4096), A -> g_af,
//                             Bm -> g_wf[:, 4096:4224)
// ---------------------------------------------------------------------------
#define XB (T_TOK / 8)   // 1024 blocks, one warp per token

__global__ void __launch_bounds__(256)
prep_kernel(const float* __restrict__ x, const float* __restrict__ Wr,
            const float* __restrict__ Wb, const float* __restrict__ A,
            const float* __restrict__ Bm) {
    if (blockIdx.x < XB) {
        const int wid  = threadIdx.x >> 5;
        const int lane = threadIdx.x & 31;
        const int t = blockIdx.x * 8 + wid;
        const float* xr = x + (size_t)t * DIN;
        __half* xo = g_xf + (size_t)t * KCAT;

        float acc[NE];
#pragma unroll
        for (int e = 0; e < NE; ++e) acc[e] = 0.f;

#pragma unroll 4
        for (int i = 0; i < 32; ++i) {
            int off = i * 128 + lane * 4;
            float4 v = *(const float4*)(xr + off);
            __half2 h0, h1;
            h0.x = __float2half_rn(v.x); h0.y = __float2half_rn(v.y);
            h1.x = __float2half_rn(v.z); h1.y = __float2half_rn(v.w);
            uint2 pk;
            pk.x = *(const uint32_t*)&h0;
            pk.y = *(const uint32_t*)&h1;
            *(uint2*)(xo + off) = pk;
#pragma unroll
            for (int e = 0; e < NE; ++e) {
                float4 w = *(const float4*)(Wr + (size_t)e * DIN + off);
                acc[e] += v.x * w.x + v.y * w.y + v.z * w.z + v.w * w.w;
            }
        }
#pragma unroll
        for (int e = 0; e < NE; ++e) {
#pragma unroll
            for (int off = 16; off > 0; off >>= 1)
                acc[e] += __shfl_xor_sync(0xffffffffu, acc[e], off);
        }
        if (lane == 0) {
#pragma unroll
            for (int e = 0; e < NE; ++e) g_logits[(size_t)t * NE + e] = acc[e];
        }
        return;
    }

    // weight-prep part
    const long long N1 = (long long)DOUT * (DIN / 4);
    const long long N2 = (long long)ER * (DIN / 4);
    const long long N3 = (long long)DOUT * ER;
    long long i = (long long)(blockIdx.x - XB) * 256 + threadIdx.x;
    if (i < N1) {
        long long r = i / (DIN / 4);
        int c4 = (int)(i % (DIN / 4));
        float4 v = *(const float4*)(Wb + r * DIN + 4 * c4);
        __half2 h0, h1;
        h0.x = __float2half_rn(v.x); h0.y = __float2half_rn(v.y);
        h1.x = __float2half_rn(v.z); h1.y = __float2half_rn(v.w);
        uint2 pk;
        pk.x = *(const uint32_t*)&h0;
        pk.y = *(const uint32_t*)&h1;
        *(uint2*)(g_wf + r * KCAT + 4 * c4) = pk;
    } else if (i < N1 + N2) {
        long long j = i - N1;
        float4 v = *(const float4*)(A + 4 * j);
        __half2 h0, h1;
        h0.x = __float2half_rn(v.x); h0.y = __float2half_rn(v.y);
        h1.x = __float2half_rn(v.z); h1.y = __float2half_rn(v.w);
        uint2 pk;
        pk.x = *(const uint32_t*)&h0;
        pk.y = *(const uint32_t*)&h1;
        *(uint2*)(g_af + 4 * j) = pk;
    } else if (i < N1 + N2 + N3) {
        long long j = i - N1 - N2;
        int o = (int)(j >> 7);
        int c = (int)(j & 127);
        int e = c >> 4;
        int r = c & 15;
        g_wf[(size_t)o * KCAT + DIN + c] =
            __float2half_rn(Bm[((size_t)e * DOUT + o) * 16 + r]);
    }
}

// ---------------------------------------------------------------------------
// Host launcher — 3 launches: prep, h-GEMM(+routing), main GEMM.
// ---------------------------------------------------------------------------
constexpr int SMEM_MAIN = 2 * (128 + 256) * PITCH;  // 208896
constexpr int SMEM_H    = 2 * (128 + 128) * PITCH;  // 139264

extern "C" void kernel_launch(void* const* d_in, const int* in_sizes, int n_in,
                              void* d_out, int out_size) {
    const float* x    = (const float*)d_in[0];
    const float* Wb   = (const float*)d_in[1];
    const float* bias = (const float*)d_in[2];
    const float* Wr   = (const float*)d_in[3];
    const float* A    = (const float*)d_in[4];
    const float* Bm   = (const float*)d_in[5];
    float* out = (float*)d_out;

    void *p_xf, *p_wf, *p_af;
    cudaGetSymbolAddress(&p_xf, g_xf);
    cudaGetSymbolAddress(&p_wf, g_wf);
    cudaGetSymbolAddress(&p_af, g_af);

    static bool attr_set = false;
    if (!attr_set) {
        cudaFuncSetAttribute(gemm_mma<KCAT, 256, 0>,
                             cudaFuncAttributeMaxDynamicSharedMemorySize, SMEM_MAIN);
        cudaFuncSetAttribute(gemm_mma<DIN, 128, 1>,
                             cudaFuncAttributeMaxDynamicSharedMemorySize, SMEM_H);
        attr_set = true;
    }

    // 1) prep: x->fp16 + router logits, Wb/A/Bflat -> fp16
    {
        long long wtotal = (long long)DOUT * (DIN / 4) + (long long)ER * (DIN / 4)
                         + (long long)DOUT * ER;
        unsigned wb = (unsigned)((wtotal + 255) / 256);
        prep_kernel<<<XB + wb, 256>>>(x, Wr, Wb, A, Bm);
    }

    // 2) h = x @ A^T  fused with routing -> G columns of g_xf
    {
        dim3 grid(1, T_TOK / 128);
        gemm_mma<DIN, 128, 1><<<grid, 256, SMEM_H>>>(
            (const __half*)p_xf, (const __half*)p_af,
            nullptr, nullptr, 0, KCAT, DIN);
    }

    // 3) out = [x|G] @ [Wb|Bf]^T + bias   (n-fast CTA order; profiled)
    {
        dim3 grid(DOUT / 256, T_TOK / 128);
        gemm_mma<KCAT, 256, 0><<<grid, 256, SMEM_MAIN>>>(
            (const __half*)p_xf, (const __half*)p_wf,
            bias, out, DOUT, KCAT, KCAT);
    }
}

// round 10
// speedup vs baseline: 1.5642x; 1.0153x over previous
#include <cuda_runtime.h>
#include <cuda_fp16.h>
#include <cstdint>
#include <cstddef>

#define T_TOK 8192
#define DIN   4096
#define DOUT  4096
#define NE    8
#define ER    128          // E * R
#define KCAT  4224         // DIN + ER
#define SCALING 2.0f

// ---------------------------------------------------------------------------
// Scratch (device globals; no allocations allowed)
// ---------------------------------------------------------------------------
__device__ __align__(128) __half g_xf[(size_t)T_TOK * KCAT];
__device__ __align__(128) __half g_wf[(size_t)DOUT * KCAT];
__device__ __align__(128) __half g_af[(size_t)ER * DIN];
__device__ float g_logits[(size_t)T_TOK * NE];

// ---------------------------------------------------------------------------
// PTX primitives (baseline sm_80+)
// ---------------------------------------------------------------------------
__device__ __forceinline__ uint32_t smem_u32(const void* p) {
    uint32_t a;
    asm("{ .reg .u64 t; cvta.to.shared.u64 t, %1; cvt.u32.u64 %0, t; }"
        : "=r"(a) : "l"(p));
    return a;
}
__device__ __forceinline__ void cp16(uint32_t s, const void* g) {
    asm volatile("cp.async.cg.shared.global [%0], [%1], 16;" :: "r"(s), "l"(g));
}
#define CP_COMMIT() asm volatile("cp.async.commit_group;" ::: "memory")
#define CP_WAIT(n)  asm volatile("cp.async.wait_group %0;" :: "n"(n) : "memory")

__device__ __forceinline__ void ldsm4(uint32_t* r, uint32_t addr) {
    asm volatile("ldmatrix.sync.aligned.m8n8.x4.shared.b16 {%0,%1,%2,%3}, [%4];"
                 : "=r"(r[0]), "=r"(r[1]), "=r"(r[2]), "=r"(r[3]) : "r"(addr));
}
__device__ __forceinline__ void mma16816(float* d, const uint32_t* a,
                                         const uint32_t* b) {
    asm volatile(
        "mma.sync.aligned.m16n8k16.row.col.f32.f16.f16.f32 "
        "{%0,%1,%2,%3}, {%4,%5,%6,%7}, {%8,%9}, {%0,%1,%2,%3};"
        : "+f"(d[0]), "+f"(d[1]), "+f"(d[2]), "+f"(d[3])
        : "r"(a[0]), "r"(a[1]), "r"(a[2]), "r"(a[3]), "r"(b[0]), "r"(b[1]));
}

// ---------------------------------------------------------------------------
// fp16 GEMM: C[M,N] = A @ B^T. Block tile BM x BN, 8 warps.
//   BM=128: warps 2x4, warp tile 64 x BN/4.
//   BM=64 : warps 1x8, warp tile 64 x BN/8.
// BK = 128 halves, 2-stage cp.async, register double-buffered fragments,
// two barriers per chunk (canonical cp.async visibility pattern).
// Smem pitch 272 B: conflict-free for cp.async stores and ldmatrix reads.
// blockIdx.x = n-tile (fast), blockIdx.y = m-tile (A-tile reuse in a wave).
// EPI 0: +bias, fp32 C.   EPI 1: MoE routing epilogue -> fp16 G cols of g_xf.
// ---------------------------------------------------------------------------
#define PITCH 272

template <int K_TOT, int BM, int BN, int EPI>
__global__ void __launch_bounds__(256, 1)
gemm_mma(const __half* __restrict__ A, const __half* __restrict__ B,
         const float* __restrict__ bias, float* __restrict__ C,
         int ldc, int lda, int ldb) {
    constexpr int NCH     = K_TOT / 128;
    constexpr int ROWS    = BM + BN;
    constexpr int STAGE_B = ROWS * PITCH;
    constexpr int MW      = BM / 64;             // m-warps (1 or 2)
    constexpr int WN      = BN / (8 / MW);       // warp n-extent
    constexpr int NP      = WN / 16;             // B ldsm4 per k16
    constexpr int LPT     = ROWS / 16;           // cp16 per thread per stage

    extern __shared__ char sm[];
    const uint32_t base = smem_u32(sm);

    const int tid  = threadIdx.x;
    const int wid  = tid >> 5;
    const int lane = tid & 31;
    const int bm = blockIdx.y * BM;    // m-tile on slow axis
    const int bn = blockIdx.x * BN;    // n-tile on fast axis
    const int wm = (wid % MW) * 64;
    const int wn = (wid / MW) * WN;

    auto stage_load = [&](int c, int s) {
        const int kk = c * 128;
        const uint32_t sb = base + s * STAGE_B;
#pragma unroll
        for (int i = 0; i < LPT; ++i) {
            int idx  = tid + i * 256;
            int row  = idx >> 4;
            int part = idx & 15;
            const __half* g = (row < BM)
                ? A + (size_t)(bm + row) * lda + kk + part * 8
                : B + (size_t)(bn + row - BM) * ldb + kk + part * 8;
            cp16(sb + row * PITCH + part * 16, g);
        }
        CP_COMMIT();
    };

    float acc[4][2 * NP][4];
#pragma unroll
    for (int i = 0; i < 4; i++)
#pragma unroll
        for (int j = 0; j < 2 * NP; j++)
#pragma unroll
            for (int k = 0; k < 4; k++) acc[i][j][k] = 0.f;

    stage_load(0, 0);
    stage_load(1, 1);

    const uint32_t a_off = (wm + (lane & 15)) * PITCH + (lane >> 4) * 16;
    const uint32_t b_row = wn + (lane & 7) + ((lane >> 4) & 1) * 8;
    const uint32_t b_off = b_row * PITCH + ((lane >> 3) & 1) * 16;

    uint32_t aF[2][4][4];
    uint32_t bF[2][NP][4];

    for (int c = 0; c < NCH; ++c) {
        const int s = c & 1;
        // CP_WAIT certifies this thread's chunk-c group; the barrier makes
        // every thread's chunk-c data visible to every warp.
        CP_WAIT(1);
        __syncthreads();

        const uint32_t sA = base + s * STAGE_B;
        const uint32_t sB = sA + BM * PITCH;

        // prime ks=0 frags
#pragma unroll
        for (int mf = 0; mf < 4; ++mf)
            ldsm4(aF[0][mf], sA + a_off + mf * (16 * PITCH));
#pragma unroll
        for (int p = 0; p < NP; ++p)
            ldsm4(bF[0][p], sB + b_off + p * (16 * PITCH));

#pragma unroll
        for (int ks = 0; ks < 8; ++ks) {
            const int cur = ks & 1, nxt = cur ^ 1;
            if (ks < 7) {
#pragma unroll
                for (int mf = 0; mf < 4; ++mf)
                    ldsm4(aF[nxt][mf], sA + a_off + mf * (16 * PITCH) + (ks + 1) * 32);
#pragma unroll
                for (int p = 0; p < NP; ++p)
                    ldsm4(bF[nxt][p], sB + b_off + p * (16 * PITCH) + (ks + 1) * 32);
            }
#pragma unroll
            for (int mf = 0; mf < 4; ++mf)
#pragma unroll
                for (int p = 0; p < NP; ++p) {
                    mma16816(acc[mf][2 * p + 0], aF[cur][mf], &bF[cur][p][0]);
                    mma16816(acc[mf][2 * p + 1], aF[cur][mf], &bF[cur][p][2]);
                }
        }

        // all warps done reading stage s -> safe to overwrite with chunk c+2
        __syncthreads();
        if (c + 2 < NCH) stage_load(c + 2, s);
        else CP_COMMIT();   // keep one commit per iteration (wait invariant)
    }

    const int row0 = wm + (lane >> 2);
    const int col0 = wn + (lane & 3) * 2;

    if (EPI == 0) {
        // bias + fp32 store
#pragma unroll
        for (int mf = 0; mf < 4; ++mf) {
#pragma unroll
            for (int r8 = 0; r8 < 2; ++r8) {
                int row = bm + row0 + mf * 16 + r8 * 8;
                float* Cr = C + (size_t)row * ldc;
#pragma unroll
                for (int nf = 0; nf < 2 * NP; ++nf) {
                    int col = bn + col0 + nf * 8;
                    float2 v;
                    v.x = acc[mf][nf][r8 * 2 + 0];
                    v.y = acc[mf][nf][r8 * 2 + 1];
                    v.x += bias[col]; v.y += bias[col + 1];
                    *(float2*)(Cr + col) = v;
                }
            }
        }
    } else {
        // Routing epilogue: h -> weighted fp16 G columns of g_xf.
        __shared__ float s_w1[BM], s_w2[BM];
        __shared__ int   s_i1[BM], s_i2[BM];
        __syncthreads();
        if (tid < BM) {
            const int t = bm + tid;
            float l[NE];
#pragma unroll
            for (int e = 0; e < NE; ++e) l[e] = g_logits[(size_t)t * NE + e];
            float best = -1e30f; int i1 = 0;
#pragma unroll
            for (int e = 0; e < NE; ++e)
                if (l[e] > best) { best = l[e]; i1 = e; }
            float second = -1e30f; int i2 = 0;
#pragma unroll
            for (int e = 0; e < NE; ++e) {
                if (e == i1) continue;
                if (l[e] > second) { second = l[e]; i2 = e; }
            }
            float r  = expf(second - best);
            float w1 = 1.0f / (1.0f + r);
            s_w1[tid] = SCALING * w1;
            s_w2[tid] = SCALING * r * w1;
            s_i1[tid] = i1;
            s_i2[tid] = i2;
        }
        __syncthreads();
#pragma unroll
        for (int mf = 0; mf < 4; ++mf) {
#pragma unroll
            for (int r8 = 0; r8 < 2; ++r8) {
                int rl = row0 + mf * 16 + r8 * 8;
                int t  = bm + rl;
                float sw1 = s_w1[rl], sw2 = s_w2[rl];
                int i1 = s_i1[rl], i2 = s_i2[rl];
                __half* dst = g_xf + (size_t)t * KCAT + DIN;
#pragma unroll
                for (int nf = 0; nf < 2 * NP; ++nf) {
                    int col = col0 + nf * 8;  // 0..127, even
                    int e = col >> 4;
                    float m = (e == i1) ? sw1 : ((e == i2) ? sw2 : 0.f);
                    __half2 hv;
                    hv.x = __float2half_rn(m * acc[mf][nf][r8 * 2 + 0]);
                    hv.y = __float2half_rn(m * acc[mf][nf][r8 * 2 + 1]);
                    *(__half2*)(dst + col) = hv;
                }
            }
        }
    }
}

// ---------------------------------------------------------------------------
// Merged prep kernel (single launch):
//   blocks [0, XB)     : x fp32->fp16 into g_xf[:, 0:4096) + router logits.
//                        4 tokens per warp -> Wr loads amortized 4x.
//   blocks [XB, ...)   : Wb -> g_wf[:, 0:4096), A -> g_af,
//                        Bm -> g_wf[:, 4096:4224)
// ---------------------------------------------------------------------------
#define TPW 4                      // tokens per warp
#define XB  (T_TOK / (8 * TPW))    // 256 blocks

__global__ void __launch_bounds__(256)
prep_kernel(const float* __restrict__ x, const float* __restrict__ Wr,
            const float* __restrict__ Wb, const float* __restrict__ A,
            const float* __restrict__ Bm) {
    if (blockIdx.x < XB) {
        const int wid  = threadIdx.x >> 5;
        const int lane = threadIdx.x & 31;
        const int t0 = (blockIdx.x * 8 + wid) * TPW;

        float acc[TPW][NE];
#pragma unroll
        for (int tk = 0; tk < TPW; ++tk)
#pragma unroll
            for (int e = 0; e < NE; ++e) acc[tk][e] = 0.f;

#pragma unroll 2
        for (int i = 0; i < 32; ++i) {
            int off = i * 128 + lane * 4;
            float4 w[NE];
#pragma unroll
            for (int e = 0; e < NE; ++e)
                w[e] = *(const float4*)(Wr + (size_t)e * DIN + off);
#pragma unroll
            for (int tk = 0; tk < TPW; ++tk) {
                float4 v = *(const float4*)(x + (size_t)(t0 + tk) * DIN + off);
                __half2 h0, h1;
                h0.x = __float2half_rn(v.x); h0.y = __float2half_rn(v.y);
                h1.x = __float2half_rn(v.z); h1.y = __float2half_rn(v.w);
                uint2 pk;
                pk.x = *(const uint32_t*)&h0;
                pk.y = *(const uint32_t*)&h1;
                *(uint2*)(g_xf + (size_t)(t0 + tk) * KCAT + off) = pk;
#pragma unroll
                for (int e = 0; e < NE; ++e)
                    acc[tk][e] += v.x * w[e].x + v.y * w[e].y
                                + v.z * w[e].z + v.w * w[e].w;
            }
        }
#pragma unroll
        for (int tk = 0; tk < TPW; ++tk)
#pragma unroll
            for (int e = 0; e < NE; ++e) {
#pragma unroll
                for (int off = 16; off > 0; off >>= 1)
                    acc[tk][e] += __shfl_xor_sync(0xffffffffu, acc[tk][e], off);
            }
        if (lane == 0) {
#pragma unroll
            for (int tk = 0; tk < TPW; ++tk)
#pragma unroll
                for (int e = 0; e < NE; ++e)
                    g_logits[(size_t)(t0 + tk) * NE + e] = acc[tk][e];
        }
        return;
    }

    // weight-prep part
    const long long N1 = (long long)DOUT * (DIN / 4);
    const long long N2 = (long long)ER * (DIN / 4);
    const long long N3 = (long long)DOUT * ER;
    long long i = (long long)(blockIdx.x - XB) * 256 + threadIdx.x;
    if (i < N1) {
        long long r = i / (DIN / 4);
        int c4 = (int)(i % (DIN / 4));
        float4 v = *(const float4*)(Wb + r * DIN + 4 * c4);
        __half2 h0, h1;
        h0.x = __float2half_rn(v.x); h0.y = __float2half_rn(v.y);
        h1.x = __float2half_rn(v.z); h1.y = __float2half_rn(v.w);
        uint2 pk;
        pk.x = *(const uint32_t*)&h0;
        pk.y = *(const uint32_t*)&h1;
        *(uint2*)(g_wf + r * KCAT + 4 * c4) = pk;
    } else if (i < N1 + N2) {
        long long j = i - N1;
        float4 v = *(const float4*)(A + 4 * j);
        __half2 h0, h1;
        h0.x = __float2half_rn(v.x); h0.y = __float2half_rn(v.y);
        h1.x = __float2half_rn(v.z); h1.y = __float2half_rn(v.w);
        uint2 pk;
        pk.x = *(const uint32_t*)&h0;
        pk.y = *(const uint32_t*)&h1;
        *(uint2*)(g_af + 4 * j) = pk;
    } else if (i < N1 + N2 + N3) {
        long long j = i - N1 - N2;
        int o = (int)(j >> 7);
        int c = (int)(j & 127);
        int e = c >> 4;
        int r = c & 15;
        g_wf[(size_t)o * KCAT + DIN + c] =
            __float2half_rn(Bm[((size_t)e * DOUT + o) * 16 + r]);
    }
}

// ---------------------------------------------------------------------------
// Host launcher — 3 launches: prep, h-GEMM(+routing), main GEMM.
// ---------------------------------------------------------------------------
constexpr int SMEM_MAIN = 2 * (128 + 256) * PITCH;  // 208896
constexpr int SMEM_H    = 2 * (64 + 128) * PITCH;   // 104448

extern "C" void kernel_launch(void* const* d_in, const int* in_sizes, int n_in,
                              void* d_out, int out_size) {
    const float* x    = (const float*)d_in[0];
    const float* Wb   = (const float*)d_in[1];
    const float* bias = (const float*)d_in[2];
    const float* Wr   = (const float*)d_in[3];
    const float* A    = (const float*)d_in[4];
    const float* Bm   = (const float*)d_in[5];
    float* out = (float*)d_out;

    void *p_xf, *p_wf, *p_af;
    cudaGetSymbolAddress(&p_xf, g_xf);
    cudaGetSymbolAddress(&p_wf, g_wf);
    cudaGetSymbolAddress(&p_af, g_af);

    static bool attr_set = false;
    if (!attr_set) {
        cudaFuncSetAttribute(gemm_mma<KCAT, 128, 256, 0>,
                             cudaFuncAttributeMaxDynamicSharedMemorySize, SMEM_MAIN);
        cudaFuncSetAttribute(gemm_mma<DIN, 64, 128, 1>,
                             cudaFuncAttributeMaxDynamicSharedMemorySize, SMEM_H);
        attr_set = true;
    }

    // 1) prep: x->fp16 + router logits (4 tok/warp), Wb/A/Bflat -> fp16
    {
        long long wtotal = (long long)DOUT * (DIN / 4) + (long long)ER * (DIN / 4)
                         + (long long)DOUT * ER;
        unsigned wb = (unsigned)((wtotal + 255) / 256);
        prep_kernel<<<XB + wb, 256>>>(x, Wr, Wb, A, Bm);
    }

    // 2) h = x @ A^T  fused with routing -> G columns of g_xf
    //    (BM=64 tiles -> 128 CTAs for better SM coverage)
    {
        dim3 grid(1, T_TOK / 64);
        gemm_mma<DIN, 64, 128, 1><<<grid, 256, SMEM_H>>>(
            (const __half*)p_xf, (const __half*)p_af,
            nullptr, nullptr, 0, KCAT, DIN);
    }

    // 3) out = [x|G] @ [Wb|Bf]^T + bias   (n-fast CTA order; profiled)
    {
        dim3 grid(DOUT / 256, T_TOK / 128);
        gemm_mma<KCAT, 128, 256, 0><<<grid, 256, SMEM_MAIN>>>(
            (const __half*)p_xf, (const __half*)p_wf,
            bias, out, DOUT, KCAT, KCAT);
    }
}

// round 11
// speedup vs baseline: 1.5657x; 1.0009x over previous
#include <cuda_runtime.h>
#include <cuda_fp16.h>
#include <cstdint>
#include <cstddef>

#define T_TOK 8192
#define DIN   4096
#define DOUT  4096
#define NE    8
#define ER    128          // E * R
#define KCAT  4224         // DIN + ER
#define SCALING 2.0f

// ---------------------------------------------------------------------------
// Scratch (device globals; no allocations allowed)
// ---------------------------------------------------------------------------
__device__ __align__(128) __half g_xf[(size_t)T_TOK * KCAT];
__device__ __align__(128) __half g_wf[(size_t)DOUT * KCAT];
__device__ __align__(128) __half g_af[(size_t)ER * DIN];
__device__ float g_logits[(size_t)T_TOK * NE];

// ---------------------------------------------------------------------------
// PTX primitives (baseline sm_80+)
// ---------------------------------------------------------------------------
__device__ __forceinline__ uint32_t smem_u32(const void* p) {
    uint32_t a;
    asm("{ .reg .u64 t; cvta.to.shared.u64 t, %1; cvt.u32.u64 %0, t; }"
        : "=r"(a) : "l"(p));
    return a;
}
__device__ __forceinline__ void cp16(uint32_t s, const void* g) {
    asm volatile("cp.async.cg.shared.global [%0], [%1], 16;" :: "r"(s), "l"(g));
}
#define CP_COMMIT() asm volatile("cp.async.commit_group;" ::: "memory")
#define CP_WAIT(n)  asm volatile("cp.async.wait_group %0;" :: "n"(n) : "memory")

__device__ __forceinline__ void ldsm4(uint32_t* r, uint32_t addr) {
    asm volatile("ldmatrix.sync.aligned.m8n8.x4.shared.b16 {%0,%1,%2,%3}, [%4];"
                 : "=r"(r[0]), "=r"(r[1]), "=r"(r[2]), "=r"(r[3]) : "r"(addr));
}
__device__ __forceinline__ void mma16816(float* d, const uint32_t* a,
                                         const uint32_t* b) {
    asm volatile(
        "mma.sync.aligned.m16n8k16.row.col.f32.f16.f16.f32 "
        "{%0,%1,%2,%3}, {%4,%5,%6,%7}, {%8,%9}, {%0,%1,%2,%3};"
        : "+f"(d[0]), "+f"(d[1]), "+f"(d[2]), "+f"(d[3])
        : "r"(a[0]), "r"(a[1]), "r"(a[2]), "r"(a[3]), "r"(b[0]), "r"(b[1]));
}

__device__ __forceinline__ uint32_t pack_h2(float a, float b) {
    __half2 h;
    h.x = __float2half_rn(a);
    h.y = __float2half_rn(b);
    return *(const uint32_t*)&h;
}

// ---------------------------------------------------------------------------
// fp16 GEMM: C[M,N] = A @ B^T. Block tile BM x BN, 8 warps.
//   BM=128: warps 2x4, warp tile 64 x BN/4.
//   BM=64 : warps 1x8, warp tile 64 x BN/8.
// BK = 128 halves, 2-stage cp.async, register double-buffered fragments,
// two barriers per chunk (canonical cp.async visibility pattern).
// Smem pitch 272 B: conflict-free for cp.async stores and ldmatrix reads.
// blockIdx.x = n-tile (fast), blockIdx.y = m-tile (A-tile reuse in a wave).
// EPI 0: +bias, fp32 C.   EPI 1: MoE routing epilogue -> fp16 G cols of g_xf.
// ---------------------------------------------------------------------------
#define PITCH 272

template <int K_TOT, int BM, int BN, int EPI>
__global__ void __launch_bounds__(256, 1)
gemm_mma(const __half* __restrict__ A, const __half* __restrict__ B,
         const float* __restrict__ bias, float* __restrict__ C,
         int ldc, int lda, int ldb) {
    constexpr int NCH     = K_TOT / 128;
    constexpr int ROWS    = BM + BN;
    constexpr int STAGE_B = ROWS * PITCH;
    constexpr int MW      = BM / 64;             // m-warps (1 or 2)
    constexpr int WN      = BN / (8 / MW);       // warp n-extent
    constexpr int NP      = WN / 16;             // B ldsm4 per k16
    constexpr int LPT     = ROWS / 16;           // cp16 per thread per stage

    extern __shared__ char sm[];
    const uint32_t base = smem_u32(sm);

    const int tid  = threadIdx.x;
    const int wid  = tid >> 5;
    const int lane = tid & 31;
    const int bm = blockIdx.y * BM;    // m-tile on slow axis
    const int bn = blockIdx.x * BN;    // n-tile on fast axis
    const int wm = (wid % MW) * 64;
    const int wn = (wid / MW) * WN;

    auto stage_load = [&](int c, int s) {
        const int kk = c * 128;
        const uint32_t sb = base + s * STAGE_B;
#pragma unroll
        for (int i = 0; i < LPT; ++i) {
            int idx  = tid + i * 256;
            int row  = idx >> 4;
            int part = idx & 15;
            const __half* g = (row < BM)
                ? A + (size_t)(bm + row) * lda + kk + part * 8
                : B + (size_t)(bn + row - BM) * ldb + kk + part * 8;
            cp16(sb + row * PITCH + part * 16, g);
        }
        CP_COMMIT();
    };

    float acc[4][2 * NP][4];
#pragma unroll
    for (int i = 0; i < 4; i++)
#pragma unroll
        for (int j = 0; j < 2 * NP; j++)
#pragma unroll
            for (int k = 0; k < 4; k++) acc[i][j][k] = 0.f;

    stage_load(0, 0);
    stage_load(1, 1);

    const uint32_t a_off = (wm + (lane & 15)) * PITCH + (lane >> 4) * 16;
    const uint32_t b_row = wn + (lane & 7) + ((lane >> 4) & 1) * 8;
    const uint32_t b_off = b_row * PITCH + ((lane >> 3) & 1) * 16;

    uint32_t aF[2][4][4];
    uint32_t bF[2][NP][4];

    for (int c = 0; c < NCH; ++c) {
        const int s = c & 1;
        // CP_WAIT certifies this thread's chunk-c group; the barrier makes
        // every thread's chunk-c data visible to every warp.
        CP_WAIT(1);
        __syncthreads();

        const uint32_t sA = base + s * STAGE_B;
        const uint32_t sB = sA + BM * PITCH;

        // prime ks=0 frags
#pragma unroll
        for (int mf = 0; mf < 4; ++mf)
            ldsm4(aF[0][mf], sA + a_off + mf * (16 * PITCH));
#pragma unroll
        for (int p = 0; p < NP; ++p)
            ldsm4(bF[0][p], sB + b_off + p * (16 * PITCH));

#pragma unroll
        for (int ks = 0; ks < 8; ++ks) {
            const int cur = ks & 1, nxt = cur ^ 1;
            if (ks < 7) {
#pragma unroll
                for (int mf = 0; mf < 4; ++mf)
                    ldsm4(aF[nxt][mf], sA + a_off + mf * (16 * PITCH) + (ks + 1) * 32);
#pragma unroll
                for (int p = 0; p < NP; ++p)
                    ldsm4(bF[nxt][p], sB + b_off + p * (16 * PITCH) + (ks + 1) * 32);
            }
#pragma unroll
            for (int mf = 0; mf < 4; ++mf)
#pragma unroll
                for (int p = 0; p < NP; ++p) {
                    mma16816(acc[mf][2 * p + 0], aF[cur][mf], &bF[cur][p][0]);
                    mma16816(acc[mf][2 * p + 1], aF[cur][mf], &bF[cur][p][2]);
                }
        }

        // all warps done reading stage s -> safe to overwrite with chunk c+2
        __syncthreads();
        if (c + 2 < NCH) stage_load(c + 2, s);
        else CP_COMMIT();   // keep one commit per iteration (wait invariant)
    }

    const int row0 = wm + (lane >> 2);
    const int col0 = wn + (lane & 3) * 2;

    if (EPI == 0) {
        // bias + fp32 store
#pragma unroll
        for (int mf = 0; mf < 4; ++mf) {
#pragma unroll
            for (int r8 = 0; r8 < 2; ++r8) {
                int row = bm + row0 + mf * 16 + r8 * 8;
                float* Cr = C + (size_t)row * ldc;
#pragma unroll
                for (int nf = 0; nf < 2 * NP; ++nf) {
                    int col = bn + col0 + nf * 8;
                    float2 v;
                    v.x = acc[mf][nf][r8 * 2 + 0];
                    v.y = acc[mf][nf][r8 * 2 + 1];
                    v.x += bias[col]; v.y += bias[col + 1];
                    *(float2*)(Cr + col) = v;
                }
            }
        }
    } else {
        // Routing epilogue: h -> weighted fp16 G columns of g_xf.
        __shared__ float s_w1[BM], s_w2[BM];
        __shared__ int   s_i1[BM], s_i2[BM];
        __syncthreads();
        if (tid < BM) {
            const int t = bm + tid;
            float l[NE];
#pragma unroll
            for (int e = 0; e < NE; ++e) l[e] = g_logits[(size_t)t * NE + e];
            float best = -1e30f; int i1 = 0;
#pragma unroll
            for (int e = 0; e < NE; ++e)
                if (l[e] > best) { best = l[e]; i1 = e; }
            float second = -1e30f; int i2 = 0;
#pragma unroll
            for (int e = 0; e < NE; ++e) {
                if (e == i1) continue;
                if (l[e] > second) { second = l[e]; i2 = e; }
            }
            float r  = expf(second - best);
            float w1 = 1.0f / (1.0f + r);
            s_w1[tid] = SCALING * w1;
            s_w2[tid] = SCALING * r * w1;
            s_i1[tid] = i1;
            s_i2[tid] = i2;
        }
        __syncthreads();
#pragma unroll
        for (int mf = 0; mf < 4; ++mf) {
#pragma unroll
            for (int r8 = 0; r8 < 2; ++r8) {
                int rl = row0 + mf * 16 + r8 * 8;
                int t  = bm + rl;
                float sw1 = s_w1[rl], sw2 = s_w2[rl];
                int i1 = s_i1[rl], i2 = s_i2[rl];
                __half* dst = g_xf + (size_t)t * KCAT + DIN;
#pragma unroll
                for (int nf = 0; nf < 2 * NP; ++nf) {
                    int col = col0 + nf * 8;  // 0..127, even
                    int e = col >> 4;
                    float m = (e == i1) ? sw1 : ((e == i2) ? sw2 : 0.f);
                    __half2 hv;
                    hv.x = __float2half_rn(m * acc[mf][nf][r8 * 2 + 0]);
                    hv.y = __float2half_rn(m * acc[mf][nf][r8 * 2 + 1]);
                    *(__half2*)(dst + col) = hv;
                }
            }
        }
    }
}

// ---------------------------------------------------------------------------
// Merged prep kernel (single launch):
//   blocks [0, XB)   : x fp32->fp16 into g_xf[:, 0:4096) + router logits.
//                      One warp per token, 8 floats per lane-iteration,
//                      STG.128 stores, 18 batched LDG.128 per iteration.
//   blocks [XB, ...) : Wb -> g_wf[:, 0:4096) (8 floats/thread, uint4 store),
//                      A -> g_af (8 floats/thread),
//                      Bm -> g_wf[:, 4096:4224) (2 scalars/thread)
// ---------------------------------------------------------------------------
#define XB (T_TOK / 8)   // 1024 blocks, one warp per token

__global__ void __launch_bounds__(256)
prep_kernel(const float* __restrict__ x, const float* __restrict__ Wr,
            const float* __restrict__ Wb, const float* __restrict__ A,
            const float* __restrict__ Bm) {
    if (blockIdx.x < XB) {
        const int wid  = threadIdx.x >> 5;
        const int lane = threadIdx.x & 31;
        const int t = blockIdx.x * 8 + wid;
        const float* xr = x + (size_t)t * DIN;
        __half* xo = g_xf + (size_t)t * KCAT;

        float acc[NE];
#pragma unroll
        for (int e = 0; e < NE; ++e) acc[e] = 0.f;

#pragma unroll 2
        for (int i = 0; i < 16; ++i) {
            int off = i * 256 + lane * 8;
            float4 v0 = *(const float4*)(xr + off);
            float4 v1 = *(const float4*)(xr + off + 4);
            uint4 pk;
            pk.x = pack_h2(v0.x, v0.y);
            pk.y = pack_h2(v0.z, v0.w);
            pk.z = pack_h2(v1.x, v1.y);
            pk.w = pack_h2(v1.z, v1.w);
            *(uint4*)(xo + off) = pk;
#pragma unroll
            for (int e = 0; e < NE; ++e) {
                const float* wr = Wr + (size_t)e * DIN + off;
                float4 w0 = *(const float4*)(wr);
                float4 w1 = *(const float4*)(wr + 4);
                acc[e] += v0.x * w0.x + v0.y * w0.y + v0.z * w0.z + v0.w * w0.w
                        + v1.x * w1.x + v1.y * w1.y + v1.z * w1.z + v1.w * w1.w;
            }
        }
#pragma unroll
        for (int e = 0; e < NE; ++e) {
#pragma unroll
            for (int off = 16; off > 0; off >>= 1)
                acc[e] += __shfl_xor_sync(0xffffffffu, acc[e], off);
        }
        if (lane == 0) {
#pragma unroll
            for (int e = 0; e < NE; ++e) g_logits[(size_t)t * NE + e] = acc[e];
        }
        return;
    }

    // weight-prep part (8-float groups for Wb/A, half2 pairs for Bflat)
    const long long N1 = (long long)DOUT * (DIN / 8);   // Wb groups
    const long long N2 = (long long)ER * (DIN / 8);     // A groups
    const long long N3 = (long long)DOUT * (ER / 2);    // Bflat half2
    long long i = (long long)(blockIdx.x - XB) * 256 + threadIdx.x;
    if (i < N1) {
        long long r = i / (DIN / 8);
        int c8 = (int)(i % (DIN / 8));
        const float* src = Wb + r * DIN + 8 * c8;
        float4 v0 = *(const float4*)(src);
        float4 v1 = *(const float4*)(src + 4);
        uint4 pk;
        pk.x = pack_h2(v0.x, v0.y);
        pk.y = pack_h2(v0.z, v0.w);
        pk.z = pack_h2(v1.x, v1.y);
        pk.w = pack_h2(v1.z, v1.w);
        *(uint4*)(g_wf + r * KCAT + 8 * c8) = pk;
    } else if (i < N1 + N2) {
        long long j = i - N1;
        const float* src = A + 8 * j;
        float4 v0 = *(const float4*)(src);
        float4 v1 = *(const float4*)(src + 4);
        uint4 pk;
        pk.x = pack_h2(v0.x, v0.y);
        pk.y = pack_h2(v0.z, v0.w);
        pk.z = pack_h2(v1.x, v1.y);
        pk.w = pack_h2(v1.z, v1.w);
        *(uint4*)(g_af + 8 * j) = pk;
    } else if (i < N1 + N2 + N3) {
        long long j = i - N1 - N2;
        int o  = (int)(j >> 6);
        int c  = (int)(j & 63) * 2;   // even column in [0,128)
        int e  = c >> 4;
        int r  = c & 15;              // even -> r, r+1 within same expert row
        float2 v = *(const float2*)(Bm + ((size_t)e * DOUT + o) * 16 + r);
        *(uint32_t*)(g_wf + (size_t)o * KCAT + DIN + c) = pack_h2(v.x, v.y);
    }
}

// ---------------------------------------------------------------------------
// Host launcher — 3 launches: prep, h-GEMM(+routing), main GEMM.
// ---------------------------------------------------------------------------
constexpr int SMEM_MAIN = 2 * (128 + 256) * PITCH;  // 208896
constexpr int SMEM_H    = 2 * (64 + 128) * PITCH;   // 104448

extern "C" void kernel_launch(void* const* d_in, const int* in_sizes, int n_in,
                              void* d_out, int out_size) {
    const float* x    = (const float*)d_in[0];
    const float* Wb   = (const float*)d_in[1];
    const float* bias = (const float*)d_in[2];
    const float* Wr   = (const float*)d_in[3];
    const float* A    = (const float*)d_in[4];
    const float* Bm   = (const float*)d_in[5];
    float* out = (float*)d_out;

    void *p_xf, *p_wf, *p_af;
    cudaGetSymbolAddress(&p_xf, g_xf);
    cudaGetSymbolAddress(&p_wf, g_wf);
    cudaGetSymbolAddress(&p_af, g_af);

    static bool attr_set = false;
    if (!attr_set) {
        cudaFuncSetAttribute(gemm_mma<KCAT, 128, 256, 0>,
                             cudaFuncAttributeMaxDynamicSharedMemorySize, SMEM_MAIN);
        cudaFuncSetAttribute(gemm_mma<DIN, 64, 128, 1>,
                             cudaFuncAttributeMaxDynamicSharedMemorySize, SMEM_H);
        attr_set = true;
    }

    // 1) prep: x->fp16 + router logits, Wb/A/Bflat -> fp16
    {
        long long wtotal = (long long)DOUT * (DIN / 8) + (long long)ER * (DIN / 8)
                         + (long long)DOUT * (ER / 2);
        unsigned wb = (unsigned)((wtotal + 255) / 256);
        prep_kernel<<<XB + wb, 256>>>(x, Wr, Wb, A, Bm);
    }

    // 2) h = x @ A^T  fused with routing -> G columns of g_xf
    //    (BM=64 tiles -> 128 CTAs for SM coverage)
    {
        dim3 grid(1, T_TOK / 64);
        gemm_mma<DIN, 64, 128, 1><<<grid, 256, SMEM_H>>>(
            (const __half*)p_xf, (const __half*)p_af,
            nullptr, nullptr, 0, KCAT, DIN);
    }

    // 3) out = [x|G] @ [Wb|Bf]^T + bias   (n-fast CTA order; profiled)
    {
        dim3 grid(DOUT / 256, T_TOK / 128);
        gemm_mma<KCAT, 128, 256, 0><<<grid, 256, SMEM_MAIN>>>(
            (const __half*)p_xf, (const __half*)p_wf,
            bias, out, DOUT, KCAT, KCAT);
    }
}

// round 12
// speedup vs baseline: 1.5884x; 1.0145x over previous
#include <cuda_runtime.h>
#include <cuda_fp16.h>
#include <cstdint>
#include <cstddef>

#define T_TOK 8192
#define DIN   4096
#define DOUT  4096
#define NE    8
#define ER    128          // E * R
#define KCAT  4224         // DIN + ER
#define SCALING 2.0f

// ---------------------------------------------------------------------------
// Scratch (device globals; no allocations allowed)
// ---------------------------------------------------------------------------
__device__ __align__(128) __half g_xf[(size_t)T_TOK * KCAT];
__device__ __align__(128) __half g_wf[(size_t)DOUT * KCAT];
__device__ __align__(128) __half g_af[(size_t)ER * DIN];
__device__ float g_logits[(size_t)T_TOK * NE];

// ---------------------------------------------------------------------------
// PTX primitives (baseline sm_80+)
// ---------------------------------------------------------------------------
__device__ __forceinline__ uint32_t smem_u32(const void* p) {
    uint32_t a;
    asm("{ .reg .u64 t; cvta.to.shared.u64 t, %1; cvt.u32.u64 %0, t; }"
        : "=r"(a) : "l"(p));
    return a;
}
__device__ __forceinline__ void cp16(uint32_t s, const void* g) {
    asm volatile("cp.async.cg.shared.global [%0], [%1], 16;" :: "r"(s), "l"(g));
}
#define CP_COMMIT() asm volatile("cp.async.commit_group;" ::: "memory")
#define CP_WAIT(n)  asm volatile("cp.async.wait_group %0;" :: "n"(n) : "memory")

__device__ __forceinline__ void ldsm4(uint32_t* r, uint32_t addr) {
    asm volatile("ldmatrix.sync.aligned.m8n8.x4.shared.b16 {%0,%1,%2,%3}, [%4];"
                 : "=r"(r[0]), "=r"(r[1]), "=r"(r[2]), "=r"(r[3]) : "r"(addr));
}
__device__ __forceinline__ void mma16816(float* d, const uint32_t* a,
                                         const uint32_t* b) {
    asm volatile(
        "mma.sync.aligned.m16n8k16.row.col.f32.f16.f16.f32 "
        "{%0,%1,%2,%3}, {%4,%5,%6,%7}, {%8,%9}, {%0,%1,%2,%3};"
        : "+f"(d[0]), "+f"(d[1]), "+f"(d[2]), "+f"(d[3])
        : "r"(a[0]), "r"(a[1]), "r"(a[2]), "r"(a[3]), "r"(b[0]), "r"(b[1]));
}

__device__ __forceinline__ uint32_t pack_h2(float a, float b) {
    __half2 h;
    h.x = __float2half_rn(a);
    h.y = __float2half_rn(b);
    return *(const uint32_t*)&h;
}

// ---------------------------------------------------------------------------
// fp16 GEMM: C[M,N] = A @ B^T. Block tile BM x BN, 8 warps.
//   BM=128: warps 2x4, warp tile 64 x BN/4.
//   BM=64 : warps 1x8, warp tile 64 x BN/8.
// BK = 128 halves, 2-stage cp.async, register double-buffered fragments,
// two barriers per chunk (canonical cp.async visibility pattern).
// Smem pitch 272 B: conflict-free for cp.async stores and ldmatrix reads.
// blockIdx.x = n-tile (fast), blockIdx.y = m-tile (A-tile reuse in a wave).
// EPI 0: +bias, fp32 C.   EPI 1: MoE routing epilogue -> fp16 G cols of g_xf.
// ---------------------------------------------------------------------------
#define PITCH 272

template <int K_TOT, int BM, int BN, int EPI>
__global__ void __launch_bounds__(256, 1)
gemm_mma(const __half* __restrict__ A, const __half* __restrict__ B,
         const float* __restrict__ bias, float* __restrict__ C,
         int ldc, int lda, int ldb) {
    constexpr int NCH     = K_TOT / 128;
    constexpr int ROWS    = BM + BN;
    constexpr int STAGE_B = ROWS * PITCH;
    constexpr int MW      = BM / 64;             // m-warps (1 or 2)
    constexpr int WN      = BN / (8 / MW);       // warp n-extent
    constexpr int NP      = WN / 16;             // B ldsm4 per k16
    constexpr int LPT     = ROWS / 16;           // cp16 per thread per stage

    extern __shared__ char sm[];
    const uint32_t base = smem_u32(sm);

    const int tid  = threadIdx.x;
    const int wid  = tid >> 5;
    const int lane = tid & 31;
    const int bm = blockIdx.y * BM;    // m-tile on slow axis
    const int bn = blockIdx.x * BN;    // n-tile on fast axis
    const int wm = (wid % MW) * 64;
    const int wn = (wid / MW) * WN;

    auto stage_load = [&](int c, int s) {
        const int kk = c * 128;
        const uint32_t sb = base + s * STAGE_B;
#pragma unroll
        for (int i = 0; i < LPT; ++i) {
            int idx  = tid + i * 256;
            int row  = idx >> 4;
            int part = idx & 15;
            const __half* g = (row < BM)
                ? A + (size_t)(bm + row) * lda + kk + part * 8
                : B + (size_t)(bn + row - BM) * ldb + kk + part * 8;
            cp16(sb + row * PITCH + part * 16, g);
        }
        CP_COMMIT();
    };

    float acc[4][2 * NP][4];
#pragma unroll
    for (int i = 0; i < 4; i++)
#pragma unroll
        for (int j = 0; j < 2 * NP; j++)
#pragma unroll
            for (int k = 0; k < 4; k++) acc[i][j][k] = 0.f;

    stage_load(0, 0);
    stage_load(1, 1);

    const uint32_t a_off = (wm + (lane & 15)) * PITCH + (lane >> 4) * 16;
    const uint32_t b_row = wn + (lane & 7) + ((lane >> 4) & 1) * 8;
    const uint32_t b_off = b_row * PITCH + ((lane >> 3) & 1) * 16;

    uint32_t aF[2][4][4];
    uint32_t bF[2][NP][4];

    for (int c = 0; c < NCH; ++c) {
        const int s = c & 1;
        // CP_WAIT certifies this thread's chunk-c group; the barrier makes
        // every thread's chunk-c data visible to every warp.
        CP_WAIT(1);
        __syncthreads();

        const uint32_t sA = base + s * STAGE_B;
        const uint32_t sB = sA + BM * PITCH;

        // prime ks=0 frags
#pragma unroll
        for (int mf = 0; mf < 4; ++mf)
            ldsm4(aF[0][mf], sA + a_off + mf * (16 * PITCH));
#pragma unroll
        for (int p = 0; p < NP; ++p)
            ldsm4(bF[0][p], sB + b_off + p * (16 * PITCH));

#pragma unroll
        for (int ks = 0; ks < 8; ++ks) {
            const int cur = ks & 1, nxt = cur ^ 1;
            if (ks < 7) {
#pragma unroll
                for (int mf = 0; mf < 4; ++mf)
                    ldsm4(aF[nxt][mf], sA + a_off + mf * (16 * PITCH) + (ks + 1) * 32);
#pragma unroll
                for (int p = 0; p < NP; ++p)
                    ldsm4(bF[nxt][p], sB + b_off + p * (16 * PITCH) + (ks + 1) * 32);
            }
#pragma unroll
            for (int mf = 0; mf < 4; ++mf)
#pragma unroll
                for (int p = 0; p < NP; ++p) {
                    mma16816(acc[mf][2 * p + 0], aF[cur][mf], &bF[cur][p][0]);
                    mma16816(acc[mf][2 * p + 1], aF[cur][mf], &bF[cur][p][2]);
                }
        }

        // all warps done reading stage s -> safe to overwrite with chunk c+2
        __syncthreads();
        if (c + 2 < NCH) stage_load(c + 2, s);
        else CP_COMMIT();   // keep one commit per iteration (wait invariant)
    }

    const int row0 = wm + (lane >> 2);
    const int col0 = wn + (lane & 3) * 2;

    if (EPI == 0) {
        // bias + fp32 store
#pragma unroll
        for (int mf = 0; mf < 4; ++mf) {
#pragma unroll
            for (int r8 = 0; r8 < 2; ++r8) {
                int row = bm + row0 + mf * 16 + r8 * 8;
                float* Cr = C + (size_t)row * ldc;
#pragma unroll
                for (int nf = 0; nf < 2 * NP; ++nf) {
                    int col = bn + col0 + nf * 8;
                    float2 v;
                    v.x = acc[mf][nf][r8 * 2 + 0];
                    v.y = acc[mf][nf][r8 * 2 + 1];
                    v.x += bias[col]; v.y += bias[col + 1];
                    *(float2*)(Cr + col) = v;
                }
            }
        }
    } else {
        // Routing epilogue: h -> weighted fp16 G columns of g_xf.
        __shared__ float s_w1[BM], s_w2[BM];
        __shared__ int   s_i1[BM], s_i2[BM];
        __syncthreads();
        if (tid < BM) {
            const int t = bm + tid;
            float l[NE];
#pragma unroll
            for (int e = 0; e < NE; ++e) l[e] = g_logits[(size_t)t * NE + e];
            float best = -1e30f; int i1 = 0;
#pragma unroll
            for (int e = 0; e < NE; ++e)
                if (l[e] > best) { best = l[e]; i1 = e; }
            float second = -1e30f; int i2 = 0;
#pragma unroll
            for (int e = 0; e < NE; ++e) {
                if (e == i1) continue;
                if (l[e] > second) { second = l[e]; i2 = e; }
            }
            float r  = expf(second - best);
            float w1 = 1.0f / (1.0f + r);
            s_w1[tid] = SCALING * w1;
            s_w2[tid] = SCALING * r * w1;
            s_i1[tid] = i1;
            s_i2[tid] = i2;
        }
        __syncthreads();
#pragma unroll
        for (int mf = 0; mf < 4; ++mf) {
#pragma unroll
            for (int r8 = 0; r8 < 2; ++r8) {
                int rl = row0 + mf * 16 + r8 * 8;
                int t  = bm + rl;
                float sw1 = s_w1[rl], sw2 = s_w2[rl];
                int i1 = s_i1[rl], i2 = s_i2[rl];
                __half* dst = g_xf + (size_t)t * KCAT + DIN;
#pragma unroll
                for (int nf = 0; nf < 2 * NP; ++nf) {
                    int col = col0 + nf * 8;  // 0..127, even
                    int e = col >> 4;
                    float m = (e == i1) ? sw1 : ((e == i2) ? sw2 : 0.f);
                    __half2 hv;
                    hv.x = __float2half_rn(m * acc[mf][nf][r8 * 2 + 0]);
                    hv.y = __float2half_rn(m * acc[mf][nf][r8 * 2 + 1]);
                    *(__half2*)(dst + col) = hv;
                }
            }
        }
    }
}

// ---------------------------------------------------------------------------
// Merged prep kernel (single launch):
//   blocks [0, XB)   : x fp32->fp16 into g_xf[:, 0:4096) + router logits.
//                      TWO tokens per warp -> Wr L1 traffic halved vs
//                      warp-per-token, at ~72 regs (vs 104 @ TPW=4).
//   blocks [XB, ...) : Wb -> g_wf[:, 0:4096) (8 floats/thread, uint4 store),
//                      A -> g_af (8 floats/thread),
//                      Bm -> g_wf[:, 4096:4224) (2 scalars/thread)
// ---------------------------------------------------------------------------
#define TPW 2
#define XB  (T_TOK / (8 * TPW))   // 512 blocks

__global__ void __launch_bounds__(256)
prep_kernel(const float* __restrict__ x, const float* __restrict__ Wr,
            const float* __restrict__ Wb, const float* __restrict__ A,
            const float* __restrict__ Bm) {
    if (blockIdx.x < XB) {
        const int wid  = threadIdx.x >> 5;
        const int lane = threadIdx.x & 31;
        const int t0 = (blockIdx.x * 8 + wid) * TPW;
        const float* xr0 = x + (size_t)t0 * DIN;
        const float* xr1 = xr0 + DIN;
        __half* xo0 = g_xf + (size_t)t0 * KCAT;
        __half* xo1 = xo0 + KCAT;

        float acc0[NE], acc1[NE];
#pragma unroll
        for (int e = 0; e < NE; ++e) { acc0[e] = 0.f; acc1[e] = 0.f; }

#pragma unroll 2
        for (int i = 0; i < 32; ++i) {
            int off = i * 128 + lane * 4;
            float4 w[NE];
#pragma unroll
            for (int e = 0; e < NE; ++e)
                w[e] = *(const float4*)(Wr + (size_t)e * DIN + off);

            float4 v0 = *(const float4*)(xr0 + off);
            float4 v1 = *(const float4*)(xr1 + off);
            uint2 p0, p1;
            p0.x = pack_h2(v0.x, v0.y); p0.y = pack_h2(v0.z, v0.w);
            p1.x = pack_h2(v1.x, v1.y); p1.y = pack_h2(v1.z, v1.w);
            *(uint2*)(xo0 + off) = p0;
            *(uint2*)(xo1 + off) = p1;
#pragma unroll
            for (int e = 0; e < NE; ++e) {
                acc0[e] += v0.x * w[e].x + v0.y * w[e].y
                         + v0.z * w[e].z + v0.w * w[e].w;
                acc1[e] += v1.x * w[e].x + v1.y * w[e].y
                         + v1.z * w[e].z + v1.w * w[e].w;
            }
        }
#pragma unroll
        for (int e = 0; e < NE; ++e) {
#pragma unroll
            for (int off = 16; off > 0; off >>= 1) {
                acc0[e] += __shfl_xor_sync(0xffffffffu, acc0[e], off);
                acc1[e] += __shfl_xor_sync(0xffffffffu, acc1[e], off);
            }
        }
        if (lane == 0) {
#pragma unroll
            for (int e = 0; e < NE; ++e) {
                g_logits[(size_t)t0 * NE + e]       = acc0[e];
                g_logits[(size_t)(t0 + 1) * NE + e] = acc1[e];
            }
        }
        return;
    }

    // weight-prep part (8-float groups for Wb/A, half2 pairs for Bflat)
    const long long N1 = (long long)DOUT * (DIN / 8);   // Wb groups
    const long long N2 = (long long)ER * (DIN / 8);     // A groups
    const long long N3 = (long long)DOUT * (ER / 2);    // Bflat half2
    long long i = (long long)(blockIdx.x - XB) * 256 + threadIdx.x;
    if (i < N1) {
        long long r = i / (DIN / 8);
        int c8 = (int)(i % (DIN / 8));
        const float* src = Wb + r * DIN + 8 * c8;
        float4 v0 = *(const float4*)(src);
        float4 v1 = *(const float4*)(src + 4);
        uint4 pk;
        pk.x = pack_h2(v0.x, v0.y);
        pk.y = pack_h2(v0.z, v0.w);
        pk.z = pack_h2(v1.x, v1.y);
        pk.w = pack_h2(v1.z, v1.w);
        *(uint4*)(g_wf + r * KCAT + 8 * c8) = pk;
    } else if (i < N1 + N2) {
        long long j = i - N1;
        const float* src = A + 8 * j;
        float4 v0 = *(const float4*)(src);
        float4 v1 = *(const float4*)(src + 4);
        uint4 pk;
        pk.x = pack_h2(v0.x, v0.y);
        pk.y = pack_h2(v0.z, v0.w);
        pk.z = pack_h2(v1.x, v1.y);
        pk.w = pack_h2(v1.z, v1.w);
        *(uint4*)(g_af + 8 * j) = pk;
    } else if (i < N1 + N2 + N3) {
        long long j = i - N1 - N2;
        int o  = (int)(j >> 6);
        int c  = (int)(j & 63) * 2;   // even column in [0,128)
        int e  = c >> 4;
        int r  = c & 15;              // even -> r, r+1 within same expert row
        float2 v = *(const float2*)(Bm + ((size_t)e * DOUT + o) * 16 + r);
        *(uint32_t*)(g_wf + (size_t)o * KCAT + DIN + c) = pack_h2(v.x, v.y);
    }
}

// ---------------------------------------------------------------------------
// Host launcher — 3 launches: prep, h-GEMM(+routing), main GEMM.
// ---------------------------------------------------------------------------
constexpr int SMEM_MAIN = 2 * (128 + 256) * PITCH;  // 208896
constexpr int SMEM_H    = 2 * (64 + 128) * PITCH;   // 104448

extern "C" void kernel_launch(void* const* d_in, const int* in_sizes, int n_in,
                              void* d_out, int out_size) {
    const float* x    = (const float*)d_in[0];
    const float* Wb   = (const float*)d_in[1];
    const float* bias = (const float*)d_in[2];
    const float* Wr   = (const float*)d_in[3];
    const float* A    = (const float*)d_in[4];
    const float* Bm   = (const float*)d_in[5];
    float* out = (float*)d_out;

    void *p_xf, *p_wf, *p_af;
    cudaGetSymbolAddress(&p_xf, g_xf);
    cudaGetSymbolAddress(&p_wf, g_wf);
    cudaGetSymbolAddress(&p_af, g_af);

    static bool attr_set = false;
    if (!attr_set) {
        cudaFuncSetAttribute(gemm_mma<KCAT, 128, 256, 0>,
                             cudaFuncAttributeMaxDynamicSharedMemorySize, SMEM_MAIN);
        cudaFuncSetAttribute(gemm_mma<DIN, 64, 128, 1>,
                             cudaFuncAttributeMaxDynamicSharedMemorySize, SMEM_H);
        attr_set = true;
    }

    // 1) prep: x->fp16 + router logits (2 tok/warp), Wb/A/Bflat -> fp16
    {
        long long wtotal = (long long)DOUT * (DIN / 8) + (long long)ER * (DIN / 8)
                         + (long long)DOUT * (ER / 2);
        unsigned wb = (unsigned)((wtotal + 255) / 256);
        prep_kernel<<<XB + wb, 256>>>(x, Wr, Wb, A, Bm);
    }

    // 2) h = x @ A^T  fused with routing -> G columns of g_xf
    //    (BM=64 tiles -> 128 CTAs for SM coverage)
    {
        dim3 grid(1, T_TOK / 64);
        gemm_mma<DIN, 64, 128, 1><<<grid, 256, SMEM_H>>>(
            (const __half*)p_xf, (const __half*)p_af,
            nullptr, nullptr, 0, KCAT, DIN);
    }

    // 3) out = [x|G] @ [Wb|Bf]^T + bias   (n-fast CTA order; profiled)
    {
        dim3 grid(DOUT / 256, T_TOK / 128);
        gemm_mma<KCAT, 128, 256, 0><<<grid, 256, SMEM_MAIN>>>(
            (const __half*)p_xf, (const __half*)p_wf,
            bias, out, DOUT, KCAT, KCAT);
    }
}